// round 13
// baseline (speedup 1.0000x reference)
#include <cuda_runtime.h>
#include <cstdint>

// Lower-triangular matvec: y[i] = sum_{j<=i} W[i,j] * x[j]
// n = 8192, W row-major fp32 (lower triangle = 128 MB, streamed once).
//
// R13: pair-block (rows b, n-1-b; tot = m0+m1 in {2047,2048} float4s),
// 128 threads/block, 16 float4/thread over the flattened combined index
// space, SOFTWARE-PIPELINED in 4 batches of 4: batch b+1's W loads are
// issued BEFORE batch b is consumed, so every warp holds a full 4-deep
// W batch (2 KB) in flight continuously -- unlike R2 where outstanding
// loads drain to zero between batches (avg ~2), and unlike R6/R12 where
// 8-deep batches cost 100 regs. x loads (L1-hit) happen at consume time.

#define NT 128

__device__ __forceinline__ float dot4(float4 w, float4 v) {
    return w.x * v.x + w.y * v.y + w.z * v.z + w.w * v.w;
}

__global__ __launch_bounds__(NT)
void tril_mv_kernel(const float* __restrict__ x,
                    const float* __restrict__ W,
                    float* __restrict__ y,
                    int n)
{
    __shared__ float red0[NT / 32];
    __shared__ float red1[NT / 32];

    const int tid = threadIdx.x;
    const int b   = blockIdx.x;
    const int r0  = b;
    const int r1  = n - 1 - b;

    const int len0 = r0 + 1;
    const int len1 = n - b;             // = r1 + 1
    const int m0   = len0 >> 2;
    const int m1   = len1 >> 2;
    const int tot  = m0 + m1;           // 2047 or 2048 for n=8192

    const float4* __restrict__ W40 =
        reinterpret_cast<const float4*>(W + (size_t)r0 * n);
    const float4* __restrict__ W41 =
        reinterpret_cast<const float4*>(W + (size_t)r1 * n);
    const float4* __restrict__ x4 = reinterpret_cast<const float4*>(x);

    float acc0 = 0.0f, acc1 = 0.0f;

    // Batches 0..2 cover j = tid + u*128, u = 0..11  (j <= 1535 < 2047):
    // always in range, no predicates. Batch 3 (u = 12..15, j <= 2047) is
    // predicated against tot.

    float4 wb[4];                        // in-flight W batch (registers)

    // ---- prologue: issue batch 0 ----
    #pragma unroll
    for (int u = 0; u < 4; u++) {
        const int j = tid + u * NT;
        wb[u] = __ldcs((j < m0) ? (W40 + j) : (W41 + (j - m0)));
    }

    // ---- pipelined batches 0..2: issue next, then consume current ----
    #pragma unroll
    for (int bat = 0; bat < 3; bat++) {
        float4 wn[4];
        if (bat < 2) {                   // next batch fully in range
            #pragma unroll
            for (int u = 0; u < 4; u++) {
                const int j = tid + (bat + 1) * 4 * NT + u * NT;
                wn[u] = __ldcs((j < m0) ? (W40 + j) : (W41 + (j - m0)));
            }
        } else {                         // loading batch 3: predicated
            #pragma unroll
            for (int u = 0; u < 4; u++) {
                const int j = tid + 12 * NT + u * NT;
                if (j < tot)
                    wn[u] = __ldcs((j < m0) ? (W40 + j) : (W41 + (j - m0)));
            }
        }
        // consume current batch (x loads are L1 hits)
        #pragma unroll
        for (int u = 0; u < 4; u++) {
            const int j   = tid + bat * 4 * NT + u * NT;
            const int col = (j < m0) ? j : (j - m0);
            const float p = dot4(wb[u], __ldg(x4 + col));
            if (j < m0) acc0 += p; else acc1 += p;
        }
        #pragma unroll
        for (int u = 0; u < 4; u++) wb[u] = wn[u];
    }

    // ---- epilogue: consume batch 3 (predicated) ----
    #pragma unroll
    for (int u = 0; u < 4; u++) {
        const int j = tid + 12 * NT + u * NT;
        if (j < tot) {
            const int col = (j < m0) ? j : (j - m0);
            const float p = dot4(wb[u], __ldg(x4 + col));
            if (j < m0) acc0 += p; else acc1 += p;
        }
    }

    // ---- scalar tails (len % 4 floats per row) ----
    {
        const int t0 = len0 & 3;
        if (tid < t0) {
            const int j = (m0 << 2) + tid;
            acc0 += W[(size_t)r0 * n + j] * x[j];
        }
        const int t1 = len1 & 3;
        if (tid >= 32 && tid < 32 + t1) {
            const int j = (m1 << 2) + (tid - 32);
            acc1 += W[(size_t)r1 * n + j] * x[j];
        }
    }

    // ---- dual block reduction (4 warps) ----
    #pragma unroll
    for (int off = 16; off > 0; off >>= 1) {
        acc0 += __shfl_down_sync(0xffffffffu, acc0, off);
        acc1 += __shfl_down_sync(0xffffffffu, acc1, off);
    }
    const int warp = tid >> 5;
    const int lane = tid & 31;
    if (lane == 0) { red0[warp] = acc0; red1[warp] = acc1; }
    __syncthreads();

    if (warp == 0 && lane < 4) {
        float a0 = red0[lane];
        float a1 = red1[lane];
        #pragma unroll
        for (int off = 2; off > 0; off >>= 1) {
            a0 += __shfl_down_sync(0x0000000fu, a0, off);
            a1 += __shfl_down_sync(0x0000000fu, a1, off);
        }
        if (lane == 0) { y[r0] = a0; y[r1] = a1; }
    }
}

extern "C" void kernel_launch(void* const* d_in, const int* in_sizes, int n_in,
                              void* d_out, int out_size) {
    const float* x = (const float*)d_in[0];   // [n]
    const float* W = (const float*)d_in[1];   // [n, n] row-major
    float*       y = (float*)d_out;           // [n]

    const int n = in_sizes[0];                // 8192 (even)

    tril_mv_kernel<<<n / 2, NT>>>(x, W, y, n);
}

// round 14
// speedup vs baseline: 1.0082x; 1.0082x over previous
#include <cuda_runtime.h>

// Lower-triangular matvec: y[i] = sum_{j<=i} W[i,j] * x[j]
// n = 8192, W row-major fp32 (lower triangle = 128 MB, streamed once).
//
// R14: R2's exact inner loop (best so far: 29.2us, DRAM 62.6%), but with a
// tail-free schedule: grid = 888 blocks (148 SMs x 6 resident = ONE wave).
// Block g statically processes pairs g, g+888, ... (pair p -> rows p, n-1-p,
// exactly n+1 floats: balanced). R2's 4096 equal-cost blocks formed 3.46
// waves -> the final partial wave idled ~54% of slots, costing ~12-14% DRAM
// duty. Here all blocks are resident from t=0, and when the 4-pair blocks
// retire, 544 five-pair blocks (~4.3 MB in flight) still saturate DRAM.

#define NTHREADS 256
#define GRID     888

__device__ __forceinline__ float dot4(float4 w, float4 v) {
    return w.x * v.x + w.y * v.y + w.z * v.z + w.w * v.w;
}

// Partial dot of one W row (length len) with x — identical to R2.
__device__ __forceinline__ float row_dot(const float* __restrict__ Wr,
                                         const float* __restrict__ x,
                                         const float4* __restrict__ x4,
                                         int len, int tid)
{
    const float4* __restrict__ W4 = reinterpret_cast<const float4*>(Wr);
    const int nv4 = len >> 2;

    float a0 = 0.0f, a1 = 0.0f, a2 = 0.0f, a3 = 0.0f;

    int k = tid;
    for (; k + 3 * NTHREADS < nv4; k += 4 * NTHREADS) {
        float4 w0 = __ldcs(W4 + k);
        float4 w1 = __ldcs(W4 + k + NTHREADS);
        float4 w2 = __ldcs(W4 + k + 2 * NTHREADS);
        float4 w3 = __ldcs(W4 + k + 3 * NTHREADS);
        float4 v0 = __ldg(x4 + k);
        float4 v1 = __ldg(x4 + k + NTHREADS);
        float4 v2 = __ldg(x4 + k + 2 * NTHREADS);
        float4 v3 = __ldg(x4 + k + 3 * NTHREADS);
        a0 += dot4(w0, v0);
        a1 += dot4(w1, v1);
        a2 += dot4(w2, v2);
        a3 += dot4(w3, v3);
    }
    #pragma unroll 1
    for (; k < nv4; k += NTHREADS) {
        a0 += dot4(__ldcs(W4 + k), __ldg(x4 + k));
    }

    float acc = (a0 + a1) + (a2 + a3);

    const int tail = len & 3;
    if (tid < tail) {
        const int j = (nv4 << 2) + tid;
        acc += Wr[j] * x[j];
    }
    return acc;
}

__global__ __launch_bounds__(NTHREADS, 6)
void tril_mv_kernel(const float* __restrict__ x,
                    const float* __restrict__ W,
                    float* __restrict__ y,
                    int n)
{
    __shared__ float red0[NTHREADS / 32];
    __shared__ float red1[NTHREADS / 32];

    const int tid    = threadIdx.x;
    const int npairs = n >> 1;
    const float4* __restrict__ x4 = reinterpret_cast<const float4*>(x);

    for (int p = blockIdx.x; p < npairs; p += GRID) {
        const int r0 = p;
        const int r1 = n - 1 - p;

        float acc0 = row_dot(W + (size_t)r0 * n, x, x4, r0 + 1, tid);
        float acc1 = row_dot(W + (size_t)r1 * n, x, x4, r1 + 1, tid);

        // ---- dual block reduction ----
        #pragma unroll
        for (int off = 16; off > 0; off >>= 1) {
            acc0 += __shfl_down_sync(0xffffffffu, acc0, off);
            acc1 += __shfl_down_sync(0xffffffffu, acc1, off);
        }
        const int warp = tid >> 5;
        const int lane = tid & 31;
        if (lane == 0) { red0[warp] = acc0; red1[warp] = acc1; }
        __syncthreads();

        if (warp == 0) {
            float a0 = (lane < NTHREADS / 32) ? red0[lane] : 0.0f;
            float a1 = (lane < NTHREADS / 32) ? red1[lane] : 0.0f;
            #pragma unroll
            for (int off = (NTHREADS / 64); off > 0; off >>= 1) {
                a0 += __shfl_down_sync(0xffffffffu, a0, off);
                a1 += __shfl_down_sync(0xffffffffu, a1, off);
            }
            if (lane == 0) { y[r0] = a0; y[r1] = a1; }
        }
        __syncthreads();   // red0/red1 reuse guard for the next pair
    }
}

extern "C" void kernel_launch(void* const* d_in, const int* in_sizes, int n_in,
                              void* d_out, int out_size) {
    const float* x = (const float*)d_in[0];   // [n]
    const float* W = (const float*)d_in[1];   // [n, n] row-major
    float*       y = (float*)d_out;           // [n]

    const int n = in_sizes[0];                // 8192 (even)

    tril_mv_kernel<<<GRID, NTHREADS>>>(x, W, y, n);
}

// round 15
// speedup vs baseline: 1.2440x; 1.2339x over previous
#include <cuda_runtime.h>

// Lower-triangular matvec: y[i] = sum_{j<=i} W[i,j] * x[j]
// n = 8192, W row-major fp32 (lower triangle = 128 MB, streamed once).
//
// R15: R2 (best: 29.2us, DRAM 62.6%) + register-free MLP via
// prefetch.global.L2. R2's plateau cause: every DRAM request needed a
// destination register, and ptxas at 40 regs keeps only ~2 loads in flight
// per warp; deeper batches cost occupancy. prefetch.global.L2 is
// fire-and-forget (no reg, no smem, no fence): each thread prefetches one
// 128B line of row r0 and one of row r1 at block start (256 thr x 128B =
// 32KB = one full row each), so the block's entire 64KB is DRAM-in-flight
// immediately; the LDGs then merge with the fills / hit L2.

#define NTHREADS 256

__device__ __forceinline__ float dot4(float4 w, float4 v) {
    return w.x * v.x + w.y * v.y + w.z * v.z + w.w * v.w;
}

__device__ __forceinline__ void prefetch_l2(const void* p) {
    asm volatile("prefetch.global.L2 [%0];" :: "l"(p));
}

// Partial dot of one W row (length len) with x — identical to R2.
__device__ __forceinline__ float row_dot(const float* __restrict__ Wr,
                                         const float* __restrict__ x,
                                         const float4* __restrict__ x4,
                                         int len, int tid)
{
    const float4* __restrict__ W4 = reinterpret_cast<const float4*>(Wr);
    const int nv4 = len >> 2;

    float a0 = 0.0f, a1 = 0.0f, a2 = 0.0f, a3 = 0.0f;

    int k = tid;
    for (; k + 3 * NTHREADS < nv4; k += 4 * NTHREADS) {
        float4 w0 = __ldcs(W4 + k);
        float4 w1 = __ldcs(W4 + k + NTHREADS);
        float4 w2 = __ldcs(W4 + k + 2 * NTHREADS);
        float4 w3 = __ldcs(W4 + k + 3 * NTHREADS);
        float4 v0 = __ldg(x4 + k);
        float4 v1 = __ldg(x4 + k + NTHREADS);
        float4 v2 = __ldg(x4 + k + 2 * NTHREADS);
        float4 v3 = __ldg(x4 + k + 3 * NTHREADS);
        a0 += dot4(w0, v0);
        a1 += dot4(w1, v1);
        a2 += dot4(w2, v2);
        a3 += dot4(w3, v3);
    }
    #pragma unroll 1
    for (; k < nv4; k += NTHREADS) {
        a0 += dot4(__ldcs(W4 + k), __ldg(x4 + k));
    }

    float acc = (a0 + a1) + (a2 + a3);

    const int tail = len & 3;
    if (tid < tail) {
        const int j = (nv4 << 2) + tid;
        acc += Wr[j] * x[j];
    }
    return acc;
}

__global__ __launch_bounds__(NTHREADS)
void tril_mv_kernel(const float* __restrict__ x,
                    const float* __restrict__ W,
                    float* __restrict__ y,
                    int n)
{
    __shared__ float red0[NTHREADS / 32];
    __shared__ float red1[NTHREADS / 32];

    const int b   = blockIdx.x;      // 0 .. n/2-1
    const int tid = threadIdx.x;

    const int r0 = b;
    const int r1 = n - 1 - b;

    const int len0 = r0 + 1;
    const int len1 = n - b;          // = r1 + 1

    // ---- register-free MLP: request the block's full 64 KB up front ----
    {
        const char* p0 = (const char*)(W + (size_t)r0 * n);
        const char* p1 = (const char*)(W + (size_t)r1 * n);
        const int lines0 = (len0 * 4 + 127) >> 7;   // <= 256
        const int lines1 = (len1 * 4 + 127) >> 7;   // <= 256
        if (tid < lines0) prefetch_l2(p0 + (size_t)tid * 128);
        if (tid < lines1) prefetch_l2(p1 + (size_t)tid * 128);
    }

    const float4* __restrict__ x4 = reinterpret_cast<const float4*>(x);

    float acc0 = row_dot(W + (size_t)r0 * n, x, x4, len0, tid);
    float acc1 = row_dot(W + (size_t)r1 * n, x, x4, len1, tid);

    // ---- dual block reduction ----
    #pragma unroll
    for (int off = 16; off > 0; off >>= 1) {
        acc0 += __shfl_down_sync(0xffffffffu, acc0, off);
        acc1 += __shfl_down_sync(0xffffffffu, acc1, off);
    }
    const int warp = tid >> 5;
    const int lane = tid & 31;
    if (lane == 0) { red0[warp] = acc0; red1[warp] = acc1; }
    __syncthreads();

    if (warp == 0) {
        float a0 = (lane < NTHREADS / 32) ? red0[lane] : 0.0f;
        float a1 = (lane < NTHREADS / 32) ? red1[lane] : 0.0f;
        #pragma unroll
        for (int off = (NTHREADS / 64); off > 0; off >>= 1) {
            a0 += __shfl_down_sync(0xffffffffu, a0, off);
            a1 += __shfl_down_sync(0xffffffffu, a1, off);
        }
        if (lane == 0) { y[r0] = a0; y[r1] = a1; }
    }
}

extern "C" void kernel_launch(void* const* d_in, const int* in_sizes, int n_in,
                              void* d_out, int out_size) {
    const float* x = (const float*)d_in[0];   // [n]
    const float* W = (const float*)d_in[1];   // [n, n] row-major
    float*       y = (float*)d_out;           // [n]

    const int n = in_sizes[0];                // 8192 (even)

    tril_mv_kernel<<<n / 2, NTHREADS>>>(x, W, y, n);
}